// round 13
// baseline (speedup 1.0000x reference)
#include <cuda_runtime.h>

// LSTM: B=4096, T=256, F=18, H=64 (4H=256 gates i,f,g,o), classifier O=15.
// R13 = R12 + loop rotation: x-part is software-pipelined one step ahead so
// the MUFU epilogue(t) overlaps x-part(t+1) FMAs in the same barrier window.
// Gate pairs {g,g+16} packed as u64 -> weight loads are LDS.64 consecutive.
// Warps 0-3 (A) reduce k=0..40; warps 4-7 (B) k=41..81; symmetric epilogue.
// Exchange via STS.128/LDS.128. tanh.approx activations (5 MUFU/cell).

#define T_LEN 256
#define F_IN  18
#define H_DIM 64
#define G_DIM 256
#define O_DIM 15
#define ROWS  32
#define NTHR  256
#define NCTA  128
#define GK    32      // h-k steps per group
#define GF    9       // x-f steps per group

typedef unsigned long long u64;

#define HSTRIDE 66    // u64 per h row (64 data + 2 pad)

// ---- shared memory layout (bytes) ----
#define SM_WT    0                           // u64 wtp[82][128]       = 83968
#define SM_H     83968                       // u64 h[32][66]          = 16896
#define SM_X     (SM_H + 16896)              // u64 x[2][32][18]       = 9216
#define SM_RED   (SM_X + 9216)               // u64x2 red[2][8][128]   = 32768
#define SM_BS    (SM_RED + 32768)            // float bs[256]          = 1024
#define SM_WCLS  (SM_BS + 1024)              // float wcls[15*64]      = 3840
#define SM_BCLS  (SM_WCLS + 3840)            // float bcls[16]         = 64
#define SM_TOTAL (SM_BCLS + 64)              // 147776

__device__ __forceinline__ u64 pack2(float x, float y) {
    u64 r; asm("mov.b64 %0, {%1, %2};" : "=l"(r) : "f"(x), "f"(y)); return r;
}
__device__ __forceinline__ void unpack2(u64 v, float& x, float& y) {
    asm("mov.b64 {%0, %1}, %2;" : "=f"(x), "=f"(y) : "l"(v));
}
__device__ __forceinline__ void fma2(u64& d, u64 a, u64 b) {
    asm("fma.rn.f32x2 %0, %1, %2, %3;" : "=l"(d) : "l"(a), "l"(b), "l"(d));
}
__device__ __forceinline__ void add2(u64& d, u64 a) {
    asm("add.rn.f32x2 %0, %1, %2;" : "=l"(d) : "l"(d), "l"(a));
}
__device__ __forceinline__ ulonglong2 lds_v2(const u64* p) {
    return *(const ulonglong2*)p;    // LDS.128 (16B-aligned by construction)
}

// hardware tanh (MUFU.TANH): 1 MUFU op, ~5e-4 max abs err
__device__ __forceinline__ float tanh_(float x) {
    float r; asm("tanh.approx.f32 %0, %1;" : "=f"(r) : "f"(x)); return r;
}
// sigmoid via tanh: sig(x) = 0.5*tanh(x/2) + 0.5
__device__ __forceinline__ float sig_(float x) {
    return fmaf(0.5f, tanh_(0.5f * x), 0.5f);
}

__global__ void __launch_bounds__(NTHR, 1) lstm_kernel(
    const float* __restrict__ X,      // [B,T,F]
    const float* __restrict__ W_ih,   // [4H,F]
    const float* __restrict__ W_hh,   // [4H,H]
    const float* __restrict__ b_ih,   // [4H]
    const float* __restrict__ b_hh,   // [4H]
    const float* __restrict__ W_cls,  // [O,H]
    const float* __restrict__ b_cls,  // [O]
    float* __restrict__ out)          // [B,O]
{
    extern __shared__ char sm[];
    u64*        wtp  = (u64*)       (sm + SM_WT);   // wtp[k][q*32+p*16+tg] = {W[g0],W[g0+16]}
    u64*        hbuf = (u64*)       (sm + SM_H);
    ulonglong2* red2 = (ulonglong2*)(sm + SM_RED);  // red2[writer][rl*4+q][lane]
    float*      bs   = (float*)     (sm + SM_BS);
    float*      wcls = (float*)     (sm + SM_WCLS);
    float*      bcl  = (float*)     (sm + SM_BCLS);

    const int tid  = threadIdx.x;
    const int lt   = tid & 127;
    const int gsel = tid >> 7;          // 0 = group A (k 0..40), 1 = group B (k 41..81)
    const int tg   = tid & 15;          // cell group: cells tg + 16c, c=0..3
    const int tr   = (tid >> 4) & 7;    // row group: rows 4tr .. 4tr+3
    const int row0 = blockIdx.x * ROWS;

    // ---- one-time setup: pack weights as {W[g], W[g+16]} pairs ----
    for (int i = tid; i < (H_DIM + F_IN) * 128; i += NTHR) {
        int k = i >> 7, col = i & 127;
        int q = col >> 5, rem = col & 31;
        int p = rem >> 4, tgx = rem & 15;
        int g0 = 64 * q + 32 * p + tgx;
        float lo, hi;
        if (k < H_DIM) {
            lo = W_hh[g0 * H_DIM + k];
            hi = W_hh[(g0 + 16) * H_DIM + k];
        } else {
            int f = k - H_DIM;
            lo = W_ih[g0 * F_IN + f];
            hi = W_ih[(g0 + 16) * F_IN + f];
        }
        wtp[i] = pack2(lo, hi);
    }
    for (int g = tid; g < G_DIM; g += NTHR) bs[g] = b_ih[g] + b_hh[g];
    for (int i = tid; i < O_DIM * H_DIM; i += NTHR) wcls[i] = W_cls[i];
    if (tid < O_DIM) bcl[tid] = b_cls[tid];
    for (int i = tid; i < ROWS * HSTRIDE; i += NTHR) hbuf[i] = 0ull;  // h(-1)=0

    // X prefetch mapping over all 256 threads: 3 slots cover 32x18 = 576
    int pb[3], pf[3]; bool pv[3];
#pragma unroll
    for (int m = 0; m < 3; m++) {
        int e = tid + NTHR * m;
        pv[m] = (e < ROWS * F_IN);
        int b = e / F_IN;
        pb[m] = b;
        pf[m] = e - b * F_IN;
    }
    const float* Xbase = X + (long long)row0 * T_LEN * F_IN;

    // stage x(0) into xbuf[0] and x(1) into xbuf[1]
    {
        u64* x0 = (u64*)(sm + SM_X);
        u64* x1 = x0 + ROWS * F_IN;
#pragma unroll
        for (int m = 0; m < 3; m++)
            if (pv[m]) {
                long long base = (long long)pb[m] * (T_LEN * F_IN) + pf[m];
                float v0 = Xbase[base];
                float v1 = Xbase[base + F_IN];
                x0[pb[m] * F_IN + pf[m]] = pack2(v0, v0);
                x1[pb[m] * F_IN + pf[m]] = pack2(v1, v1);
            }
    }
    __syncthreads();   // setup + bs + x(0),x(1) + h(-1) visible

    // gate-pair biases: biasv[q][p] = {bs[g0], bs[g0+16]}, g0 = 64q+32p+tg
    u64 biasv[4][2];
#pragma unroll
    for (int q = 0; q < 4; q++)
#pragma unroll
        for (int p = 0; p < 2; p++) {
            int g0 = 64 * q + 32 * p + tg;
            biasv[q][p] = pack2(bs[g0], bs[g0 + 16]);
        }

    // cell state: rows 4tr + 2*gsel + {0,1}, cells tg + 16c
    float creg[2][4];
#pragma unroll
    for (int r = 0; r < 2; r++)
#pragma unroll
        for (int c = 0; c < 4; c++) creg[r][c] = 0.0f;

    const int hab = 4 * tr * HSTRIDE;
    const int xab = 4 * tr * F_IN;
    const int kh0 = gsel * GK;          // h-k start for this group
    const int xf0 = gsel * GF;          // x-f start for this group
    ulonglong2*       redW = red2 + gsel * (8 * 128);
    const ulonglong2* redR = red2 + (gsel ^ 1) * (8 * 128);

    // ---- prologue: acc = bias + x(0)@W ----
    u64 acc[4][4][2];
#pragma unroll
    for (int r = 0; r < 4; r++)
#pragma unroll
        for (int q = 0; q < 4; q++)
#pragma unroll
            for (int p = 0; p < 2; p++)
                acc[r][q][p] = ((r >> 1) == gsel) ? biasv[q][p] : 0ull;
    {
        const u64* xb = (const u64*)(sm + SM_X);   // xbuf[0]
#pragma unroll 3
        for (int ff = 0; ff < GF; ff++) {
            int f = xf0 + ff;
            u64 a0 = xb[xab + f];
            u64 a1 = xb[xab + F_IN + f];
            u64 a2 = xb[xab + 2 * F_IN + f];
            u64 a3 = xb[xab + 3 * F_IN + f];
            const u64* wrow = wtp + (H_DIM + f) * 128 + tg;
#pragma unroll
            for (int q = 0; q < 4; q++)
#pragma unroll
                for (int p = 0; p < 2; p++) {
                    u64 w = wrow[q * 32 + p * 16];
                    fma2(acc[0][q][p], a0, w);
                    fma2(acc[1][q][p], a1, w);
                    fma2(acc[2][q][p], a2, w);
                    fma2(acc[3][q][p], a3, w);
                }
        }
    }

    // ================= time loop (rotated) =================
    // entry invariant at iter t: acc = bias + x(t)@W ; hbuf = h(t-1) ;
    // xbuf[(t+1)&1] = x(t+1) (for t+1 < T)
    for (int t = 0; t < T_LEN; ++t) {
        __syncthreads();   // bar1: h(t-1) visible; red readers (iter t-1) done

        // LDG prefetch x(t+2) early
        float xp[3];
        const bool have_x2 = (t + 2 < T_LEN);
        if (have_x2) {
#pragma unroll
            for (int m = 0; m < 3; m++)
                xp[m] = pv[m]
                    ? Xbase[(long long)pb[m] * (T_LEN * F_IN) + (t + 2) * F_IN + pf[m]]
                    : 0.0f;
        }

        // ---- h-part(t): acc += h(t-1)@W, this group's 32 k's ----
#pragma unroll 2
        for (int kk = 0; kk < GK; kk += 2) {
            int k = kh0 + kk;
            ulonglong2 A0 = lds_v2(&hbuf[hab + k]);
            ulonglong2 A1 = lds_v2(&hbuf[hab + HSTRIDE + k]);
            ulonglong2 A2 = lds_v2(&hbuf[hab + 2 * HSTRIDE + k]);
            ulonglong2 A3 = lds_v2(&hbuf[hab + 3 * HSTRIDE + k]);
            const u64* w0 = wtp + k * 128 + tg;
#pragma unroll
            for (int q = 0; q < 4; q++)
#pragma unroll
                for (int p = 0; p < 2; p++) {
                    u64 w = w0[q * 32 + p * 16];       // LDS.64
                    fma2(acc[0][q][p], A0.x, w);
                    fma2(acc[1][q][p], A1.x, w);
                    fma2(acc[2][q][p], A2.x, w);
                    fma2(acc[3][q][p], A3.x, w);
                }
            const u64* w1 = w0 + 128;
#pragma unroll
            for (int q = 0; q < 4; q++)
#pragma unroll
                for (int p = 0; p < 2; p++) {
                    u64 w = w1[q * 32 + p * 16];       // LDS.64
                    fma2(acc[0][q][p], A0.y, w);
                    fma2(acc[1][q][p], A1.y, w);
                    fma2(acc[2][q][p], A2.y, w);
                    fma2(acc[3][q][p], A3.y, w);
                }
        }

        // ---- publish partials for the rows the OTHER group finalizes ----
        if (gsel == 0) {
#pragma unroll
            for (int rl = 0; rl < 2; rl++)
#pragma unroll
                for (int q = 0; q < 4; q++) {
                    ulonglong2 v; v.x = acc[2 + rl][q][0]; v.y = acc[2 + rl][q][1];
                    redW[(rl * 4 + q) * 128 + lt] = v;
                }
        } else {
#pragma unroll
            for (int rl = 0; rl < 2; rl++)
#pragma unroll
                for (int q = 0; q < 4; q++) {
                    ulonglong2 v; v.x = acc[rl][q][0]; v.y = acc[rl][q][1];
                    redW[(rl * 4 + q) * 128 + lt] = v;
                }
        }

        __syncthreads();   // bar2: partials visible; hbuf readers done

        // ---- gather my rows + combine partials -> myacc(t) ----
        u64 myacc[2][4][2];
        if (gsel == 0) {
#pragma unroll
            for (int rl = 0; rl < 2; rl++)
#pragma unroll
                for (int q = 0; q < 4; q++)
#pragma unroll
                    for (int p = 0; p < 2; p++)
                        myacc[rl][q][p] = acc[rl][q][p];
        } else {
#pragma unroll
            for (int rl = 0; rl < 2; rl++)
#pragma unroll
                for (int q = 0; q < 4; q++)
#pragma unroll
                    for (int p = 0; p < 2; p++)
                        myacc[rl][q][p] = acc[2 + rl][q][p];
        }
#pragma unroll
        for (int rl = 0; rl < 2; rl++)
#pragma unroll
            for (int q = 0; q < 4; q++) {
                ulonglong2 v = redR[(rl * 4 + q) * 128 + lt];
                add2(myacc[rl][q][0], v.x);
                add2(myacc[rl][q][1], v.y);
            }

        // ---- x-part(t+1) into fresh acc (overlaps the MUFU epilogue below) ----
        if (t + 1 < T_LEN) {
#pragma unroll
            for (int r = 0; r < 4; r++)
#pragma unroll
                for (int q = 0; q < 4; q++)
#pragma unroll
                    for (int p = 0; p < 2; p++)
                        acc[r][q][p] = ((r >> 1) == gsel) ? biasv[q][p] : 0ull;
            const u64* xb = (const u64*)(sm + SM_X) + ((t + 1) & 1) * (ROWS * F_IN);
#pragma unroll 3
            for (int ff = 0; ff < GF; ff++) {
                int f = xf0 + ff;
                u64 a0 = xb[xab + f];
                u64 a1 = xb[xab + F_IN + f];
                u64 a2 = xb[xab + 2 * F_IN + f];
                u64 a3 = xb[xab + 3 * F_IN + f];
                const u64* wrow = wtp + (H_DIM + f) * 128 + tg;
#pragma unroll
                for (int q = 0; q < 4; q++)
#pragma unroll
                    for (int p = 0; p < 2; p++) {
                        u64 w = wrow[q * 32 + p * 16];
                        fma2(acc[0][q][p], a0, w);
                        fma2(acc[1][q][p], a1, w);
                        fma2(acc[2][q][p], a2, w);
                        fma2(acc[3][q][p], a3, w);
                    }
            }
        }

        // ---- MUFU epilogue(t) + publish h(t): cells j = tg + 16c ----
#pragma unroll
        for (int rl = 0; rl < 2; rl++) {
            float gv[4][4];   // [q][cell c]; c: 0->tg, 1->tg+16, 2->tg+32, 3->tg+48
#pragma unroll
            for (int q = 0; q < 4; q++) {
                unpack2(myacc[rl][q][0], gv[q][0], gv[q][1]);   // cells tg, tg+16
                unpack2(myacc[rl][q][1], gv[q][2], gv[q][3]);   // cells tg+32, tg+48
            }
            int base = (4 * tr + 2 * gsel + rl) * HSTRIDE + tg;
#pragma unroll
            for (int c = 0; c < 4; c++) {
                float iv = sig_(gv[0][c]);
                float fv = sig_(gv[1][c]);
                float gg = tanh_(gv[2][c]);
                float ov = sig_(gv[3][c]);
                float cc = fv * creg[rl][c] + iv * gg;
                creg[rl][c] = cc;
                float hv = ov * tanh_(cc);
                hbuf[base + 16 * c] = pack2(hv, hv);
            }
        }

        // ---- publish x(t+2) into xbuf[t&1] ----
        if (have_x2) {
            u64* xw = (u64*)(sm + SM_X) + (t & 1) * (ROWS * F_IN);
#pragma unroll
            for (int m = 0; m < 3; m++)
                if (pv[m]) xw[pb[m] * F_IN + pf[m]] = pack2(xp[m], xp[m]);
        }
    }

    // ---- classifier head on final h ----
    __syncthreads();
    const float* hf = (const float*)hbuf;

    for (int e = tid; e < ROWS * O_DIM; e += NTHR) {
        int b = e / O_DIM, o = e - b * O_DIM;
        float s = bcl[o];
#pragma unroll
        for (int j = 0; j < H_DIM; j++)
            s += hf[(b * HSTRIDE + j) * 2] * wcls[o * H_DIM + j];
        out[(long long)(row0 + b) * O_DIM + o] = s;
    }
}

extern "C" void kernel_launch(void* const* d_in, const int* in_sizes, int n_in,
                              void* d_out, int out_size)
{
    const float* X     = (const float*)d_in[0];
    const float* W_ih  = (const float*)d_in[1];
    const float* W_hh  = (const float*)d_in[2];
    const float* b_ih  = (const float*)d_in[3];
    const float* b_hh  = (const float*)d_in[4];
    const float* W_cls = (const float*)d_in[5];
    const float* b_cls = (const float*)d_in[6];

    cudaFuncSetAttribute(lstm_kernel,
                         cudaFuncAttributeMaxDynamicSharedMemorySize, SM_TOTAL);
    lstm_kernel<<<NCTA, NTHR, SM_TOTAL>>>(X, W_ih, W_hh, b_ih, b_hh,
                                          W_cls, b_cls, (float*)d_out);
}

// round 14
// speedup vs baseline: 1.0984x; 1.0984x over previous
#include <cuda_runtime.h>

// LSTM: B=4096, T=256, F=18, H=64 (4H=256 gates i,f,g,o), classifier O=15.
// R14 = R12 structure with issue-slot trims:
//  - weights quad-packed: wtq[k][q*16+tg] = {{W[g0],W[g0+16]},{W[g0+32],W[g0+48]}}
//    (g0 = 64q+tg) -> ONE LDS.128 per (k,q) instead of two LDS.64.
//  - partial exchange via STS.128/LDS.128 (ulonglong2).
//  - h-part unrolled x4 for deeper LDS pipelining.
// Warps 0-3 (A) reduce k=0..40; warps 4-7 (B) k=41..81; symmetric epilogue
// (A finalizes rows {0,1}, B rows {2,3}); x-part before bar1; tanh.approx.

#define T_LEN 256
#define F_IN  18
#define H_DIM 64
#define G_DIM 256
#define O_DIM 15
#define ROWS  32
#define NTHR  256
#define NCTA  128
#define GK    32      // h-k steps per group
#define GF    9       // x-f steps per group

typedef unsigned long long u64;

#define HSTRIDE 66    // u64 per h row (64 data + 2 pad)

// ---- shared memory layout (bytes) ----
#define SM_WT    0                           // u64x2 wtq[82][64]      = 83968
#define SM_H     83968                       // u64 h[32][66]          = 16896
#define SM_X     (SM_H + 16896)              // u64 x[2][32][18]       = 9216
#define SM_RED   (SM_X + 9216)               // u64x2 red[2][8][128]   = 32768
#define SM_BS    (SM_RED + 32768)            // float bs[256]          = 1024
#define SM_WCLS  (SM_BS + 1024)              // float wcls[15*64]      = 3840
#define SM_BCLS  (SM_WCLS + 3840)            // float bcls[16]         = 64
#define SM_TOTAL (SM_BCLS + 64)              // 147776

__device__ __forceinline__ u64 pack2(float x, float y) {
    u64 r; asm("mov.b64 %0, {%1, %2};" : "=l"(r) : "f"(x), "f"(y)); return r;
}
__device__ __forceinline__ void unpack2(u64 v, float& x, float& y) {
    asm("mov.b64 {%0, %1}, %2;" : "=f"(x), "=f"(y) : "l"(v));
}
__device__ __forceinline__ void fma2(u64& d, u64 a, u64 b) {
    asm("fma.rn.f32x2 %0, %1, %2, %3;" : "=l"(d) : "l"(a), "l"(b), "l"(d));
}
__device__ __forceinline__ void add2(u64& d, u64 a) {
    asm("add.rn.f32x2 %0, %1, %2;" : "=l"(d) : "l"(d), "l"(a));
}
__device__ __forceinline__ ulonglong2 lds_v2(const void* p) {
    return *(const ulonglong2*)p;    // LDS.128 (16B-aligned by construction)
}

// hardware tanh (MUFU.TANH): 1 MUFU op, ~5e-4 max abs err
__device__ __forceinline__ float tanh_(float x) {
    float r; asm("tanh.approx.f32 %0, %1;" : "=f"(r) : "f"(x)); return r;
}
// sigmoid via tanh: sig(x) = 0.5*tanh(x/2) + 0.5
__device__ __forceinline__ float sig_(float x) {
    return fmaf(0.5f, tanh_(0.5f * x), 0.5f);
}

__global__ void __launch_bounds__(NTHR, 1) lstm_kernel(
    const float* __restrict__ X,      // [B,T,F]
    const float* __restrict__ W_ih,   // [4H,F]
    const float* __restrict__ W_hh,   // [4H,H]
    const float* __restrict__ b_ih,   // [4H]
    const float* __restrict__ b_hh,   // [4H]
    const float* __restrict__ W_cls,  // [O,H]
    const float* __restrict__ b_cls,  // [O]
    float* __restrict__ out)          // [B,O]
{
    extern __shared__ char sm[];
    ulonglong2* wtq  = (ulonglong2*)(sm + SM_WT);   // wtq[k*64 + q*16 + tg]
    u64*        hbuf = (u64*)       (sm + SM_H);
    ulonglong2* red2 = (ulonglong2*)(sm + SM_RED);  // red2[writer][rl*4+q][lane]
    float*      bs   = (float*)     (sm + SM_BS);
    float*      wcls = (float*)     (sm + SM_WCLS);
    float*      bcl  = (float*)     (sm + SM_BCLS);

    const int tid  = threadIdx.x;
    const int lt   = tid & 127;
    const int gsel = tid >> 7;          // 0 = group A (k 0..40), 1 = group B (k 41..81)
    const int tg   = tid & 15;          // cell group: cells tg + 16c, c=0..3
    const int tr   = (tid >> 4) & 7;    // row group: rows 4tr .. 4tr+3
    const int row0 = blockIdx.x * ROWS;

    // ---- one-time setup: quad-pack weights ----
    // wtq[k*64 + q*16 + tgx] = { {W[g0],W[g0+16]}, {W[g0+32],W[g0+48]} }, g0 = 64q+tgx
    for (int i = tid; i < (H_DIM + F_IN) * 64; i += NTHR) {
        int k = i >> 6, col = i & 63;
        int q = col >> 4, tgx = col & 15;
        int g0 = 64 * q + tgx;
        float a, b, c, d;
        if (k < H_DIM) {
            a = W_hh[g0 * H_DIM + k];
            b = W_hh[(g0 + 16) * H_DIM + k];
            c = W_hh[(g0 + 32) * H_DIM + k];
            d = W_hh[(g0 + 48) * H_DIM + k];
        } else {
            int f = k - H_DIM;
            a = W_ih[g0 * F_IN + f];
            b = W_ih[(g0 + 16) * F_IN + f];
            c = W_ih[(g0 + 32) * F_IN + f];
            d = W_ih[(g0 + 48) * F_IN + f];
        }
        ulonglong2 v; v.x = pack2(a, b); v.y = pack2(c, d);
        wtq[i] = v;
    }
    for (int g = tid; g < G_DIM; g += NTHR) bs[g] = b_ih[g] + b_hh[g];
    for (int i = tid; i < O_DIM * H_DIM; i += NTHR) wcls[i] = W_cls[i];
    if (tid < O_DIM) bcl[tid] = b_cls[tid];
    for (int i = tid; i < ROWS * HSTRIDE; i += NTHR) hbuf[i] = 0ull;  // h(-1)=0

    // X prefetch mapping over all 256 threads: 3 slots cover 32x18 = 576
    int pb[3], pf[3]; bool pv[3];
#pragma unroll
    for (int m = 0; m < 3; m++) {
        int e = tid + NTHR * m;
        pv[m] = (e < ROWS * F_IN);
        int b = e / F_IN;
        pb[m] = b;
        pf[m] = e - b * F_IN;
    }
    const float* Xbase = X + (long long)row0 * T_LEN * F_IN;

    // stage x(0) into xbuf[0]
    {
        u64* x0 = (u64*)(sm + SM_X);
#pragma unroll
        for (int m = 0; m < 3; m++)
            if (pv[m]) {
                float v = Xbase[(long long)pb[m] * (T_LEN * F_IN) + pf[m]];
                x0[pb[m] * F_IN + pf[m]] = pack2(v, v);
            }
    }
    __syncthreads();   // bs visible for biasv packing

    // gate biases: biasv[q] = { {bs[g0],bs[g0+16]}, {bs[g0+32],bs[g0+48]} }, g0=64q+tg
    u64 biasv[4][2];
#pragma unroll
    for (int q = 0; q < 4; q++) {
        int g0 = 64 * q + tg;
        biasv[q][0] = pack2(bs[g0],      bs[g0 + 16]);
        biasv[q][1] = pack2(bs[g0 + 32], bs[g0 + 48]);
    }

    // cell state: rows 4tr + 2*gsel + {0,1}, cells tg + 16c
    float creg[2][4];
#pragma unroll
    for (int r = 0; r < 2; r++)
#pragma unroll
        for (int c = 0; c < 4; c++) creg[r][c] = 0.0f;

    const int hab = 4 * tr * HSTRIDE;
    const int xab = 4 * tr * F_IN;
    const int kh0 = gsel * GK;          // h-k start for this group
    const int xf0 = gsel * GF;          // x-f start for this group
    ulonglong2*       redW = red2 + gsel * (8 * 128);
    const ulonglong2* redR = red2 + (gsel ^ 1) * (8 * 128);
    int buf = 0;

    __syncthreads();   // setup + x(0) + h(-1) visible

    // ================= time loop =================
    for (int t = 0; t < T_LEN; ++t) {
        const u64* xb  = (const u64*)(sm + SM_X) + buf * (ROWS * F_IN);
        u64*       xb2 = (u64*)(sm + SM_X) + (buf ^ 1) * (ROWS * F_IN);

        // issue x(t+1) global loads first (latency hidden under x+h parts)
        float xp[3];
        if (t + 1 < T_LEN) {
#pragma unroll
            for (int m = 0; m < 3; m++)
                xp[m] = pv[m]
                    ? Xbase[(long long)pb[m] * (T_LEN * F_IN) + (t + 1) * F_IN + pf[m]]
                    : 0.0f;
        }

        // bias goes into the rows THIS group finalizes; zero elsewhere
        u64 acc[4][4][2];
#pragma unroll
        for (int r = 0; r < 4; r++)
#pragma unroll
            for (int q = 0; q < 4; q++)
#pragma unroll
                for (int p = 0; p < 2; p++)
                    acc[r][q][p] = ((r >> 1) == gsel) ? biasv[q][p] : 0ull;

        // ---- x-part: this group's 9 f's (needs only x(t) -> before bar1) ----
#pragma unroll 3
        for (int ff = 0; ff < GF; ff++) {
            int f = xf0 + ff;
            u64 a0 = xb[xab + f];
            u64 a1 = xb[xab + F_IN + f];
            u64 a2 = xb[xab + 2 * F_IN + f];
            u64 a3 = xb[xab + 3 * F_IN + f];
            const ulonglong2* wrow = wtq + (H_DIM + f) * 64 + tg;
#pragma unroll
            for (int q = 0; q < 4; q++) {
                ulonglong2 w = lds_v2(wrow + q * 16);   // LDS.128: both p's
                fma2(acc[0][q][0], a0, w.x); fma2(acc[0][q][1], a0, w.y);
                fma2(acc[1][q][0], a1, w.x); fma2(acc[1][q][1], a1, w.y);
                fma2(acc[2][q][0], a2, w.x); fma2(acc[2][q][1], a2, w.y);
                fma2(acc[3][q][0], a3, w.x); fma2(acc[3][q][1], a3, w.y);
            }
        }

        __syncthreads();   // bar1: h(t-1) stores visible; red(t-1) readers done

        // ---- h-part: this group's 32 k's, k-paired LDS.128 acts, unroll x4 ----
#pragma unroll 4
        for (int kk = 0; kk < GK; kk += 2) {
            int k = kh0 + kk;
            ulonglong2 A0 = lds_v2(&hbuf[hab + k]);
            ulonglong2 A1 = lds_v2(&hbuf[hab + HSTRIDE + k]);
            ulonglong2 A2 = lds_v2(&hbuf[hab + 2 * HSTRIDE + k]);
            ulonglong2 A3 = lds_v2(&hbuf[hab + 3 * HSTRIDE + k]);
            const ulonglong2* w0 = wtq + k * 64 + tg;
#pragma unroll
            for (int q = 0; q < 4; q++) {
                ulonglong2 w = lds_v2(w0 + q * 16);
                fma2(acc[0][q][0], A0.x, w.x); fma2(acc[0][q][1], A0.x, w.y);
                fma2(acc[1][q][0], A1.x, w.x); fma2(acc[1][q][1], A1.x, w.y);
                fma2(acc[2][q][0], A2.x, w.x); fma2(acc[2][q][1], A2.x, w.y);
                fma2(acc[3][q][0], A3.x, w.x); fma2(acc[3][q][1], A3.x, w.y);
            }
            const ulonglong2* w1 = w0 + 64;
#pragma unroll
            for (int q = 0; q < 4; q++) {
                ulonglong2 w = lds_v2(w1 + q * 16);
                fma2(acc[0][q][0], A0.y, w.x); fma2(acc[0][q][1], A0.y, w.y);
                fma2(acc[1][q][0], A1.y, w.x); fma2(acc[1][q][1], A1.y, w.y);
                fma2(acc[2][q][0], A2.y, w.x); fma2(acc[2][q][1], A2.y, w.y);
                fma2(acc[3][q][0], A3.y, w.x); fma2(acc[3][q][1], A3.y, w.y);
            }
        }

        // ---- publish partials for the rows the OTHER group finalizes ----
        if (gsel == 0) {
#pragma unroll
            for (int rl = 0; rl < 2; rl++)
#pragma unroll
                for (int q = 0; q < 4; q++) {
                    ulonglong2 v; v.x = acc[2 + rl][q][0]; v.y = acc[2 + rl][q][1];
                    redW[(rl * 4 + q) * 128 + lt] = v;     // STS.128
                }
        } else {
#pragma unroll
            for (int rl = 0; rl < 2; rl++)
#pragma unroll
                for (int q = 0; q < 4; q++) {
                    ulonglong2 v; v.x = acc[rl][q][0]; v.y = acc[rl][q][1];
                    redW[(rl * 4 + q) * 128 + lt] = v;
                }
        }

        // publish x(t+1) BEFORE bar2 so next step's x-part needs no extra barrier
        if (t + 1 < T_LEN) {
#pragma unroll
            for (int m = 0; m < 3; m++)
                if (pv[m]) xb2[pb[m] * F_IN + pf[m]] = pack2(xp[m], xp[m]);
        }

        __syncthreads();   // bar2: partials + x(t+1) visible; h readers done

        // ---- gather my rows (static idx, warp-uniform branch) + combine ----
        u64 myacc[2][4][2];
        if (gsel == 0) {
#pragma unroll
            for (int rl = 0; rl < 2; rl++)
#pragma unroll
                for (int q = 0; q < 4; q++)
#pragma unroll
                    for (int p = 0; p < 2; p++)
                        myacc[rl][q][p] = acc[rl][q][p];
        } else {
#pragma unroll
            for (int rl = 0; rl < 2; rl++)
#pragma unroll
                for (int q = 0; q < 4; q++)
#pragma unroll
                    for (int p = 0; p < 2; p++)
                        myacc[rl][q][p] = acc[2 + rl][q][p];
        }
#pragma unroll
        for (int rl = 0; rl < 2; rl++)
#pragma unroll
            for (int q = 0; q < 4; q++) {
                ulonglong2 v = redR[(rl * 4 + q) * 128 + lt];   // LDS.128
                add2(myacc[rl][q][0], v.x);
                add2(myacc[rl][q][1], v.y);
            }

        // ---- cell update + publish h(t): cells j = tg + 16c ----
#pragma unroll
        for (int rl = 0; rl < 2; rl++) {
            float gv[4][4];   // [q][cell c]; c: 0->tg, 1->tg+16, 2->tg+32, 3->tg+48
#pragma unroll
            for (int q = 0; q < 4; q++) {
                unpack2(myacc[rl][q][0], gv[q][0], gv[q][1]);   // cells tg, tg+16
                unpack2(myacc[rl][q][1], gv[q][2], gv[q][3]);   // cells tg+32, tg+48
            }
            int base = (4 * tr + 2 * gsel + rl) * HSTRIDE + tg;
#pragma unroll
            for (int c = 0; c < 4; c++) {
                float iv = sig_(gv[0][c]);
                float fv = sig_(gv[1][c]);
                float gg = tanh_(gv[2][c]);
                float ov = sig_(gv[3][c]);
                float cc = fv * creg[rl][c] + iv * gg;
                creg[rl][c] = cc;
                float hv = ov * tanh_(cc);
                hbuf[base + 16 * c] = pack2(hv, hv);
            }
        }

        buf ^= 1;
    }

    // ---- classifier head on final h ----
    __syncthreads();
    const float* hf = (const float*)hbuf;

    for (int e = tid; e < ROWS * O_DIM; e += NTHR) {
        int b = e / O_DIM, o = e - b * O_DIM;
        float s = bcl[o];
#pragma unroll
        for (int j = 0; j < H_DIM; j++)
            s += hf[(b * HSTRIDE + j) * 2] * wcls[o * H_DIM + j];
        out[(long long)(row0 + b) * O_DIM + o] = s;
    }
}

extern "C" void kernel_launch(void* const* d_in, const int* in_sizes, int n_in,
                              void* d_out, int out_size)
{
    const float* X     = (const float*)d_in[0];
    const float* W_ih  = (const float*)d_in[1];
    const float* W_hh  = (const float*)d_in[2];
    const float* b_ih  = (const float*)d_in[3];
    const float* b_hh  = (const float*)d_in[4];
    const float* W_cls = (const float*)d_in[5];
    const float* b_cls = (const float*)d_in[6];

    cudaFuncSetAttribute(lstm_kernel,
                         cudaFuncAttributeMaxDynamicSharedMemorySize, SM_TOTAL);
    lstm_kernel<<<NCTA, NTHR, SM_TOTAL>>>(X, W_ih, W_hh, b_ih, b_hh,
                                          W_cls, b_cls, (float*)d_out);
}